// round 1
// baseline (speedup 1.0000x reference)
#include <cuda_runtime.h>
#include <math.h>
#include <stdint.h>

#define BB 8
#define CIN 256
#define COUT 256
#define HH 64
#define WW 64
#define HWP 4096
#define KKN 9

typedef unsigned long long u64;

__device__ __forceinline__ u64 pack2(float lo, float hi) {
    u64 r; asm("mov.b64 %0, {%1,%2};" : "=l"(r) : "f"(lo), "f"(hi)); return r;
}
__device__ __forceinline__ void unpack2(u64 v, float &lo, float &hi) {
    asm("mov.b64 {%0,%1}, %2;" : "=f"(lo), "=f"(hi) : "l"(v));
}
// Packed dual-fp32 FMA: d = a*b + c per 32-bit lane. Exact fp32, 2x FFMA throughput.
__device__ __forceinline__ u64 ffma2(u64 a, u64 b, u64 c) {
    u64 d; asm("fma.rn.f32x2 %0, %1, %2, %3;" : "=l"(d) : "l"(a), "l"(b), "l"(c)); return d;
}

// ---------------- scratch (static device globals; no runtime alloc) ----------------
__device__ float  g_xnhwc[BB * HWP * CIN];      // 33.5 MB  NHWC input
__device__ float  g_ompart[2][BB * 27 * HWP];   // 7.1 MB   om conv partials (split-K)
__device__ float4 g_mw[BB * KKN * HWP];         // 4.7 MB   premultiplied bilinear wts
__device__ int4   g_mi[BB * KKN * HWP];         // 4.7 MB   NHWC gather offsets
__device__ float2 g_wp[KKN * (CIN / 2) * COUT]; // 2.4 MB   repacked dcn weights

// ---------------- 1) NCHW -> NHWC transpose ----------------
__global__ void k_transpose(const float *__restrict__ x) {
    __shared__ float tile[32][33];
    int b = blockIdx.z;
    int p0 = blockIdx.x * 32, c0 = blockIdx.y * 32;
    int tx = threadIdx.x, ty = threadIdx.y;
    const float *src = x + (size_t)b * CIN * HWP;
#pragma unroll
    for (int k = 0; k < 32; k += 8)
        tile[ty + k][tx] = src[(size_t)(c0 + ty + k) * HWP + p0 + tx];
    __syncthreads();
    float *dst = g_xnhwc + (size_t)b * HWP * CIN;
#pragma unroll
    for (int k = 0; k < 32; k += 8)
        dst[(size_t)(p0 + ty + k) * CIN + c0 + tx] = tile[tx][ty + k];
}

// ---------------- 2) repack w_dcn (O,C,3,3) -> (kk, ci/2, o) float2 ----------------
__global__ void k_wpack(const float *__restrict__ wdcn) {
    int i = blockIdx.x * 256 + threadIdx.x;
    if (i >= KKN * (CIN / 2) * COUT) return;
    int o = i % COUT;
    int t = i / COUT;
    int ci2 = t % (CIN / 2);
    int kk = t / (CIN / 2);
    g_wp[i] = make_float2(wdcn[(size_t)(o * CIN + 2 * ci2) * KKN + kk],
                          wdcn[(size_t)(o * CIN + 2 * ci2 + 1) * KKN + kk]);
}

// ---------------- 3) offset/mask conv (27ch 3x3), f32x2 over pixel pairs -------------
// block: 128 threads, handles 4 rows of one image (2 pixels/thread), half the C via split
__global__ void __launch_bounds__(128) k_om(const float *__restrict__ x,
                                            const float *__restrict__ wom) {
    __shared__ u64 wshf[16 * 243]; // weights for 16-ci chunk, duplicated (w,w)
    int b = blockIdx.y;
    int split = blockIdx.z;
    int yb = blockIdx.x * 4;
    int t = threadIdx.x;
    int ry = t >> 6, ox = t & 63;
    int y0p = yb + ry;      // pixel0 row
    int y1p = y0p + 2;      // pixel1 row

    u64 acc[27];
#pragma unroll
    for (int i = 0; i < 27; i++) acc[i] = 0ULL;

    bool rowok[5]; int rowoff[5];
#pragma unroll
    for (int r = 0; r < 5; r++) {
        int y = y0p - 1 + r;
        rowok[r] = (y >= 0) && (y < HH);
        rowoff[r] = rowok[r] ? y * WW : 0;
    }
    bool colok[3]; int coloff[3];
#pragma unroll
    for (int c = 0; c < 3; c++) {
        int xx = ox - 1 + c;
        colok[c] = (xx >= 0) && (xx < WW);
        coloff[c] = colok[c] ? xx : 0;
    }

    int cbase = split * 128;
    const float *xb = x + (size_t)b * CIN * HWP;

    for (int cc = 0; cc < 128; cc += 16) {
        __syncthreads();
        // cooperative load of 16x27x9 weights, duplicated into both f32x2 lanes
        for (int j = t; j < 16 * 243; j += 128) {
            int oc = j / 144, rem = j % 144;
            int ci = rem / 9, kk = rem % 9;
            float g = wom[(size_t)oc * 2304 + (size_t)(cbase + cc) * 9 + rem];
            wshf[ci * 243 + oc * 9 + kk] = pack2(g, g);
        }
        __syncthreads();
#pragma unroll 1
        for (int cil = 0; cil < 16; cil++) {
            const float *xc = xb + (size_t)(cbase + cc + cil) * HWP;
            float a[5][3];
#pragma unroll
            for (int r = 0; r < 5; r++)
#pragma unroll
                for (int c = 0; c < 3; c++)
                    a[r][c] = (rowok[r] && colok[c]) ? __ldg(xc + rowoff[r] + coloff[c]) : 0.f;
            u64 pv[9];
#pragma unroll
            for (int kk = 0; kk < 9; kk++) {
                int ki = kk / 3, kj = kk % 3;
                pv[kk] = pack2(a[ki][kj], a[ki + 2][kj]);
            }
            const u64 *wrow = &wshf[cil * 243];
#pragma unroll
            for (int kk = 0; kk < 9; kk++)
#pragma unroll
                for (int oc = 0; oc < 27; oc++)
                    acc[oc] = ffma2(pv[kk], wrow[oc * 9 + kk], acc[oc]);
        }
    }

    float *dst = &g_ompart[split][(size_t)b * 27 * HWP];
#pragma unroll
    for (int oc = 0; oc < 27; oc++) {
        float lo, hi; unpack2(acc[oc], lo, hi);
        dst[(size_t)oc * HWP + y0p * WW + ox] = lo;
        dst[(size_t)oc * HWP + y1p * WW + ox] = hi;
    }
}

// ---------------- 4) sampling metadata ----------------
__global__ void k_meta(const float *__restrict__ bom) {
    int i = blockIdx.x * 256 + threadIdx.x;
    if (i >= BB * KKN * HWP) return;
    int p = i % HWP;
    int t = i / HWP;
    int kk = t % KKN;
    int b = t / KKN;
    int oy = p >> 6, ox = p & 63;
    const float *o0 = &g_ompart[0][(size_t)b * 27 * HWP];
    const float *o1 = &g_ompart[1][(size_t)b * 27 * HWP];
    float dy = o0[(size_t)kk * HWP + p] + o1[(size_t)kk * HWP + p] + bom[kk];
    float dx = o0[(size_t)(9 + kk) * HWP + p] + o1[(size_t)(9 + kk) * HWP + p] + bom[9 + kk];
    float mz = o0[(size_t)(18 + kk) * HWP + p] + o1[(size_t)(18 + kk) * HWP + p] + bom[18 + kk];
    float m = 1.f / (1.f + expf(-mz));
    int ki = kk / 3, kj = kk % 3;
    float py = (float)(oy - 1 + ki) + dy;
    float px = (float)(ox - 1 + kj) + dx;
    float y0f = floorf(py), x0f = floorf(px);
    float ly = py - y0f, lx = px - x0f;
    int y0 = (int)y0f, x0 = (int)x0f;
    int y1 = y0 + 1, x1 = x0 + 1;

    float v00 = (y0 >= 0 && y0 < HH && x0 >= 0 && x0 < WW) ? 1.f : 0.f;
    float v01 = (y0 >= 0 && y0 < HH && x1 >= 0 && x1 < WW) ? 1.f : 0.f;
    float v10 = (y1 >= 0 && y1 < HH && x0 >= 0 && x0 < WW) ? 1.f : 0.f;
    float v11 = (y1 >= 0 && y1 < HH && x1 >= 0 && x1 < WW) ? 1.f : 0.f;
    int cy0 = min(max(y0, 0), HH - 1), cy1 = min(max(y1, 0), HH - 1);
    int cx0 = min(max(x0, 0), WW - 1), cx1 = min(max(x1, 0), WW - 1);

    g_mw[i] = make_float4((1.f - ly) * (1.f - lx) * m * v00,
                          (1.f - ly) * lx * m * v01,
                          ly * (1.f - lx) * m * v10,
                          ly * lx * m * v11);
    g_mi[i] = make_int4((cy0 * WW + cx0) * CIN, (cy0 * WW + cx1) * CIN,
                        (cy1 * WW + cx0) * CIN, (cy1 * WW + cx1) * CIN);
}

// ---------------- 5) fused sampling + GEMM (FFMA2) ----------------
// block: 256 threads = 256 output channels, 16 pixels; acc lanes split even/odd ci
#define TP 16
__global__ void __launch_bounds__(256) k_dcn(const float *__restrict__ bdcn,
                                             float *__restrict__ out) {
    __shared__ __align__(16) float cols[TP][32];
    __shared__ float4 smw[KKN][TP];
    __shared__ int4 smi[KKN][TP];
    int b = blockIdx.y;
    int p0 = blockIdx.x * TP;
    int tid = threadIdx.x;

    for (int j = tid; j < KKN * TP; j += 256) {
        int kk = j / TP, p = j % TP;
        int gi = (b * KKN + kk) * HWP + p0 + p;
        smw[kk][p] = g_mw[gi];
        smi[kk][p] = g_mi[gi];
    }

    u64 acc[TP];
#pragma unroll
    for (int p = 0; p < TP; p++) acc[p] = 0ULL;

    const float *xb = g_xnhwc + (size_t)b * HWP * CIN;
    const u64 *wpk = (const u64 *)g_wp;
    int o = tid;
    int ci = tid & 31;
    int pA = tid >> 5;   // 0..7
    int pB = pA + 8;

    for (int kk = 0; kk < KKN; kk++) {
        for (int cc = 0; cc < CIN; cc += 32) {
            __syncthreads(); // protects cols reuse (and smw/smi init on first pass)
            {
                float4 w = smw[kk][pA]; int4 ii = smi[kk][pA];
                cols[pA][ci] = w.x * __ldg(xb + ii.x + cc + ci) +
                               w.y * __ldg(xb + ii.y + cc + ci) +
                               w.z * __ldg(xb + ii.z + cc + ci) +
                               w.w * __ldg(xb + ii.w + cc + ci);
                float4 w2 = smw[kk][pB]; int4 i2 = smi[kk][pB];
                cols[pB][ci] = w2.x * __ldg(xb + i2.x + cc + ci) +
                               w2.y * __ldg(xb + i2.y + cc + ci) +
                               w2.z * __ldg(xb + i2.z + cc + ci) +
                               w2.w * __ldg(xb + i2.w + cc + ci);
            }
            __syncthreads();
            const u64 *wrow = wpk + (size_t)(kk * (CIN / 2) + (cc >> 1)) * COUT + o;
#pragma unroll
            for (int j2 = 0; j2 < 8; j2++) {
                u64 wa = __ldg(wrow + (size_t)(2 * j2) * COUT);
                u64 wb = __ldg(wrow + (size_t)(2 * j2 + 1) * COUT);
#pragma unroll
                for (int p = 0; p < TP; p++) {
                    u64 c01, c23;
                    unsigned addr = (unsigned)__cvta_generic_to_shared(&cols[p][4 * j2]);
                    asm("ld.shared.v2.u64 {%0,%1},[%2];" : "=l"(c01), "=l"(c23) : "r"(addr));
                    acc[p] = ffma2(c01, wa, acc[p]);
                    acc[p] = ffma2(c23, wb, acc[p]);
                }
            }
        }
    }

    float bias = bdcn[o];
    float *op = out + ((size_t)(b * COUT + o)) * HWP + p0;
#pragma unroll
    for (int p = 0; p < TP; p++) {
        float lo, hi; unpack2(acc[p], lo, hi);
        op[p] = lo + hi + bias;
    }
}

// ---------------- launch ----------------
extern "C" void kernel_launch(void *const *d_in, const int *in_sizes, int n_in,
                              void *d_out, int out_size) {
    const float *x = (const float *)d_in[0];
    const float *w_om = (const float *)d_in[1];
    const float *b_om = (const float *)d_in[2];
    const float *w_dcn = (const float *)d_in[3];
    const float *b_dcn = (const float *)d_in[4];
    float *out = (float *)d_out;

    dim3 tg(HWP / 32, CIN / 32, BB);
    k_transpose<<<tg, dim3(32, 8, 1)>>>(x);

    k_wpack<<<(KKN * (CIN / 2) * COUT + 255) / 256, 256>>>(w_dcn);

    k_om<<<dim3(16, BB, 2), 128>>>(x, w_om);

    k_meta<<<(BB * KKN * HWP + 255) / 256, 256>>>(b_om);

    k_dcn<<<dim3(HWP / TP, BB, 1), 256>>>(b_dcn, out);
}

// round 4
// speedup vs baseline: 2.2794x; 2.2794x over previous
#include <cuda_runtime.h>
#include <cuda_bf16.h>
#include <math.h>
#include <stdint.h>

#define BB 8
#define CIN 256
#define COUT 256
#define HH 64
#define WW 64
#define HWP 4096
#define KKN 9

typedef unsigned long long u64;

// ---------------- low-level helpers ----------------
__device__ __forceinline__ u64 pack2(float lo, float hi) {
    u64 r; asm("mov.b64 %0, {%1,%2};" : "=l"(r) : "f"(lo), "f"(hi)); return r;
}
__device__ __forceinline__ void unpack2(u64 v, float &lo, float &hi) {
    asm("mov.b64 {%0,%1}, %2;" : "=f"(lo), "=f"(hi) : "l"(v));
}
__device__ __forceinline__ u64 ffma2(u64 a, u64 b, u64 c) {
    u64 d; asm("fma.rn.f32x2 %0, %1, %2, %3;" : "=l"(d) : "l"(a), "l"(b), "l"(c)); return d;
}
__device__ __forceinline__ uint32_t smem_u32(const void *p) {
    uint32_t a; asm("{ .reg .u64 t; cvta.to.shared.u64 t, %1; cvt.u32.u64 %0, t; }" : "=r"(a) : "l"(p));
    return a;
}

#define CP_ASYNC16(dst, src) \
    asm volatile("cp.async.cg.shared.global [%0], [%1], 16;" :: "r"(dst), "l"(src) : "memory")
#define CP_COMMIT() asm volatile("cp.async.commit_group;" ::: "memory")
#define CP_WAIT1() asm volatile("cp.async.wait_group 1;" ::: "memory")
#define CP_WAIT0() asm volatile("cp.async.wait_group 0;" ::: "memory")

#define LDSM_X4(r, addr) \
    asm volatile("ldmatrix.sync.aligned.m8n8.x4.shared.b16 {%0,%1,%2,%3}, [%4];" \
        : "=r"((r)[0]), "=r"((r)[1]), "=r"((r)[2]), "=r"((r)[3]) : "r"(addr))
// B operand: [n][k] storage with k contiguous == col-major KxN -> NON-trans ldmatrix
#define LDSM_X2(r, addr) \
    asm volatile("ldmatrix.sync.aligned.m8n8.x2.shared.b16 {%0,%1}, [%2];" \
        : "=r"((r)[0]), "=r"((r)[1]) : "r"(addr))

#define MMA_BF16(d, a, b) \
    asm volatile("mma.sync.aligned.m16n8k16.row.col.f32.bf16.bf16.f32 " \
        "{%0,%1,%2,%3}, {%4,%5,%6,%7}, {%8,%9}, {%0,%1,%2,%3};" \
        : "+f"((d)[0]), "+f"((d)[1]), "+f"((d)[2]), "+f"((d)[3]) \
        : "r"((a)[0]), "r"((a)[1]), "r"((a)[2]), "r"((a)[3]), "r"((b)[0]), "r"((b)[1]))

#define SWZ(o) ((o) ^ (((o) >> 3) & 0x70))

// ---------------- scratch ----------------
__device__ __nv_bfloat16 g_xh[(size_t)BB * HWP * CIN];   // [b][p][c] hi
__device__ __nv_bfloat16 g_xl[(size_t)BB * HWP * CIN];   // lo
__device__ __nv_bfloat16 g_wh[KKN * COUT * CIN];         // [kk][o][c]
__device__ __nv_bfloat16 g_wl[KKN * COUT * CIN];
__device__ float  g_y[(size_t)KKN * BB * HWP * COUT];    // [kk][b][p][o]
__device__ float  g_ompart[2][BB * 27 * HWP];
__device__ float4 g_mw[BB * KKN * HWP];
__device__ int4   g_mi[BB * KKN * HWP];

// ---------------- 1) NCHW -> NHWC transpose + bf16 split ----------------
__global__ void k_transpose(const float *__restrict__ x) {
    __shared__ float tile[32][33];
    int b = blockIdx.z;
    int p0 = blockIdx.x * 32, c0 = blockIdx.y * 32;
    int tx = threadIdx.x, ty = threadIdx.y;
    const float *src = x + (size_t)b * CIN * HWP;
#pragma unroll
    for (int k = 0; k < 32; k += 8)
        tile[ty + k][tx] = src[(size_t)(c0 + ty + k) * HWP + p0 + tx];
    __syncthreads();
    __nv_bfloat16 *dh = g_xh + (size_t)b * HWP * CIN;
    __nv_bfloat16 *dl = g_xl + (size_t)b * HWP * CIN;
#pragma unroll
    for (int k = 0; k < 32; k += 8) {
        float v = tile[tx][ty + k];
        __nv_bfloat16 h = __float2bfloat16(v);
        size_t idx = (size_t)(p0 + ty + k) * CIN + c0 + tx;
        dh[idx] = h;
        dl[idx] = __float2bfloat16(v - __bfloat162float(h));
    }
}

// ---------------- 2) w_dcn -> [kk][o][c] bf16 split ----------------
__global__ void k_wsplit(const float *__restrict__ wdcn) {
    int i = blockIdx.x * 256 + threadIdx.x;
    if (i >= KKN * COUT * CIN) return;
    int c = i % CIN;
    int o = (i / CIN) % COUT;
    int kk = i / (CIN * COUT);
    float v = wdcn[(size_t)(o * CIN + c) * KKN + kk];
    __nv_bfloat16 h = __float2bfloat16(v);
    g_wh[i] = h;
    g_wl[i] = __float2bfloat16(v - __bfloat162float(h));
}

// ---------------- 3) offset/mask conv (proven in R1) ----------------
__global__ void __launch_bounds__(128) k_om(const float *__restrict__ x,
                                            const float *__restrict__ wom) {
    __shared__ u64 wshf[16 * 243];
    int b = blockIdx.y;
    int split = blockIdx.z;
    int yb = blockIdx.x * 4;
    int t = threadIdx.x;
    int ry = t >> 6, ox = t & 63;
    int y0p = yb + ry, y1p = y0p + 2;

    u64 acc[27];
#pragma unroll
    for (int i = 0; i < 27; i++) acc[i] = 0ULL;

    bool rowok[5]; int rowoff[5];
#pragma unroll
    for (int r = 0; r < 5; r++) {
        int y = y0p - 1 + r;
        rowok[r] = (y >= 0) && (y < HH);
        rowoff[r] = rowok[r] ? y * WW : 0;
    }
    bool colok[3]; int coloff[3];
#pragma unroll
    for (int c = 0; c < 3; c++) {
        int xx = ox - 1 + c;
        colok[c] = (xx >= 0) && (xx < WW);
        coloff[c] = colok[c] ? xx : 0;
    }

    int cbase = split * 128;
    const float *xb = x + (size_t)b * CIN * HWP;

    for (int cc = 0; cc < 128; cc += 16) {
        __syncthreads();
        for (int j = t; j < 16 * 243; j += 128) {
            int oc = j / 144, rem = j % 144;
            int ci = rem / 9, kk = rem % 9;
            float g = wom[(size_t)oc * 2304 + (size_t)(cbase + cc) * 9 + rem];
            wshf[ci * 243 + oc * 9 + kk] = pack2(g, g);
        }
        __syncthreads();
#pragma unroll 1
        for (int cil = 0; cil < 16; cil++) {
            const float *xc = xb + (size_t)(cbase + cc + cil) * HWP;
            float a[5][3];
#pragma unroll
            for (int r = 0; r < 5; r++)
#pragma unroll
                for (int c = 0; c < 3; c++)
                    a[r][c] = (rowok[r] && colok[c]) ? __ldg(xc + rowoff[r] + coloff[c]) : 0.f;
            u64 pv[9];
#pragma unroll
            for (int kk = 0; kk < 9; kk++) {
                int ki = kk / 3, kj = kk % 3;
                pv[kk] = pack2(a[ki][kj], a[ki + 2][kj]);
            }
            const u64 *wrow = &wshf[cil * 243];
#pragma unroll
            for (int kk = 0; kk < 9; kk++)
#pragma unroll
                for (int oc = 0; oc < 27; oc++)
                    acc[oc] = ffma2(pv[kk], wrow[oc * 9 + kk], acc[oc]);
        }
    }

    float *dst = &g_ompart[split][(size_t)b * 27 * HWP];
#pragma unroll
    for (int oc = 0; oc < 27; oc++) {
        float lo, hi; unpack2(acc[oc], lo, hi);
        dst[(size_t)oc * HWP + y0p * WW + ox] = lo;
        dst[(size_t)oc * HWP + y1p * WW + ox] = hi;
    }
}

// ---------------- 4) sampling metadata ----------------
__global__ void k_meta(const float *__restrict__ bom) {
    int i = blockIdx.x * 256 + threadIdx.x;
    if (i >= BB * KKN * HWP) return;
    int p = i % HWP;
    int t = i / HWP;
    int kk = t % KKN;
    int b = t / KKN;
    int oy = p >> 6, ox = p & 63;
    const float *o0 = &g_ompart[0][(size_t)b * 27 * HWP];
    const float *o1 = &g_ompart[1][(size_t)b * 27 * HWP];
    float dy = o0[(size_t)kk * HWP + p] + o1[(size_t)kk * HWP + p] + bom[kk];
    float dx = o0[(size_t)(9 + kk) * HWP + p] + o1[(size_t)(9 + kk) * HWP + p] + bom[9 + kk];
    float mz = o0[(size_t)(18 + kk) * HWP + p] + o1[(size_t)(18 + kk) * HWP + p] + bom[18 + kk];
    float m = 1.f / (1.f + expf(-mz));
    int ki = kk / 3, kj = kk % 3;
    float py = (float)(oy - 1 + ki) + dy;
    float px = (float)(ox - 1 + kj) + dx;
    float y0f = floorf(py), x0f = floorf(px);
    float ly = py - y0f, lx = px - x0f;
    int y0 = (int)y0f, x0 = (int)x0f;
    int y1 = y0 + 1, x1 = x0 + 1;

    float v00 = (y0 >= 0 && y0 < HH && x0 >= 0 && x0 < WW) ? 1.f : 0.f;
    float v01 = (y0 >= 0 && y0 < HH && x1 >= 0 && x1 < WW) ? 1.f : 0.f;
    float v10 = (y1 >= 0 && y1 < HH && x0 >= 0 && x0 < WW) ? 1.f : 0.f;
    float v11 = (y1 >= 0 && y1 < HH && x1 >= 0 && x1 < WW) ? 1.f : 0.f;
    int cy0 = min(max(y0, 0), HH - 1), cy1 = min(max(y1, 0), HH - 1);
    int cx0 = min(max(x0, 0), WW - 1), cx1 = min(max(x1, 0), WW - 1);

    g_mw[i] = make_float4((1.f - ly) * (1.f - lx) * m * v00,
                          (1.f - ly) * lx * m * v01,
                          ly * (1.f - lx) * m * v10,
                          ly * lx * m * v11);
    g_mi[i] = make_int4((cy0 * WW + cx0) * COUT, (cy0 * WW + cx1) * COUT,
                        (cy1 * WW + cx0) * COUT, (cy1 * WW + cx1) * COUT);
}

// ---------------- 5) dense GEMMs via mma.sync bf16 2-way split ----------------
// CTA: 128 p x 128 o, K=256 in 4 chunks of 64, double-buffered cp.async.
#define KC 64
#define STAGE_BYTES 65536
#define XH_OFF 0
#define XL_OFF 16384
#define WH_OFF 32768
#define WL_OFF 49152
#define SM_TOT (2 * STAGE_BYTES)

__global__ void __launch_bounds__(256, 1) k_gemm() {
    extern __shared__ char smem[];
    uint32_t sb = smem_u32(smem);
    int tid = threadIdx.x;
    int wid = tid >> 5, lane = tid & 31;
    int kk = blockIdx.x;
    int b = blockIdx.y >> 1;
    int o0 = (blockIdx.y & 1) * 128;
    int p0 = blockIdx.z * 128;

    const __nv_bfloat16 *xh = g_xh + ((size_t)b * HWP + p0) * CIN;
    const __nv_bfloat16 *xl = g_xl + ((size_t)b * HWP + p0) * CIN;
    const __nv_bfloat16 *wh = g_wh + ((size_t)kk * COUT + o0) * CIN;
    const __nv_bfloat16 *wl = g_wl + ((size_t)kk * COUT + o0) * CIN;

    // per-thread load slots: 4 iters x (row, atom) per tensor
    int lrow4[4], latom4[4], lsw4[4];
#pragma unroll
    for (int k2 = 0; k2 < 4; k2++) {
        int idx = tid + k2 * 256;
        lrow4[k2] = idx >> 3;
        latom4[k2] = idx & 7;
        lsw4[k2] = SWZ((idx >> 3) * 128 + (idx & 7) * 16);
    }

#define LOAD_STAGE(kc, s) do { \
        uint32_t stb = sb + (s) * STAGE_BYTES; \
        int c0_ = (kc) * KC; \
        _Pragma("unroll") \
        for (int k2 = 0; k2 < 4; k2++) { \
            size_t g = (size_t)lrow4[k2] * CIN + c0_ + latom4[k2] * 8; \
            CP_ASYNC16(stb + XH_OFF + lsw4[k2], xh + g); \
            CP_ASYNC16(stb + XL_OFF + lsw4[k2], xl + g); \
            CP_ASYNC16(stb + WH_OFF + lsw4[k2], wh + g); \
            CP_ASYNC16(stb + WL_OFF + lsw4[k2], wl + g); \
        } \
        CP_COMMIT(); \
    } while (0)

    int wp = wid >> 2;          // 0..1  (64 p rows each)
    int wo = wid & 3;           // 0..3  (32 o cols each)
    int abase = (wp * 64 + (lane & 15)) * 128 + ((lane >> 4) * 8) * 2;
    int bbase = (wo * 32 + (lane & 7)) * 128 + (((lane >> 3) & 1) * 8) * 2;

    float d[4][4][4];
#pragma unroll
    for (int mt = 0; mt < 4; mt++)
#pragma unroll
        for (int nt = 0; nt < 4; nt++)
#pragma unroll
            for (int j = 0; j < 4; j++) d[mt][nt][j] = 0.f;

    LOAD_STAGE(0, 0);

    for (int kc = 0; kc < 4; kc++) {
        if (kc < 3) LOAD_STAGE(kc + 1, (kc + 1) & 1);
        if (kc < 3) { CP_WAIT1(); } else { CP_WAIT0(); }
        __syncthreads();

        uint32_t stb = sb + (kc & 1) * STAGE_BYTES;
#pragma unroll
        for (int ks = 0; ks < 4; ks++) {
            uint32_t ah[4][4], al[4][4];
#pragma unroll
            for (int mt = 0; mt < 4; mt++) {
                int off = abase + mt * 2048 + ks * 32;
                LDSM_X4(ah[mt], stb + XH_OFF + SWZ(off));
                LDSM_X4(al[mt], stb + XL_OFF + SWZ(off));
            }
            uint32_t bh[4][2], bl[4][2];
#pragma unroll
            for (int nt = 0; nt < 4; nt++) {
                int off = bbase + nt * 1024 + ks * 32;
                LDSM_X2(bh[nt], stb + WH_OFF + SWZ(off));
                LDSM_X2(bl[nt], stb + WL_OFF + SWZ(off));
            }
#pragma unroll
            for (int mt = 0; mt < 4; mt++)
#pragma unroll
                for (int nt = 0; nt < 4; nt++) {
                    MMA_BF16(d[mt][nt], ah[mt], bh[nt]);
                    MMA_BF16(d[mt][nt], ah[mt], bl[nt]);
                    MMA_BF16(d[mt][nt], al[mt], bh[nt]);
                }
        }
        __syncthreads();
    }

    // epilogue: accums -> smem tile [128p][128o] -> coalesced global
    float *ts = (float *)smem;
#pragma unroll
    for (int mt = 0; mt < 4; mt++) {
        int r0 = wp * 64 + mt * 16 + (lane >> 2);
#pragma unroll
        for (int nt = 0; nt < 4; nt++) {
            int c = wo * 32 + nt * 8 + (lane & 3) * 2;
            ts[r0 * 128 + c] = d[mt][nt][0];
            ts[r0 * 128 + c + 1] = d[mt][nt][1];
            ts[(r0 + 8) * 128 + c] = d[mt][nt][2];
            ts[(r0 + 8) * 128 + c + 1] = d[mt][nt][3];
        }
    }
    __syncthreads();
    float *yo = g_y + (((size_t)(kk * BB + b) * HWP + p0) * COUT) + o0;
#pragma unroll
    for (int i = tid; i < 4096; i += 256) {
        int r = i >> 5, c4 = i & 31;
        *(float4 *)(yo + (size_t)r * COUT + c4 * 4) = *(float4 *)(ts + r * 128 + c4 * 4);
    }
#undef LOAD_STAGE
}

// ---------------- 6) gather-axpy assembly: out[b][o][p] ----------------
__global__ void __launch_bounds__(512) k_out(const float *__restrict__ bdcn,
                                             float *__restrict__ out) {
    __shared__ float4 smw[KKN][16];
    __shared__ int4 smi[KKN][16];
    __shared__ float st[16][257];
    int b = blockIdx.y;
    int p0 = blockIdx.x * 16;
    int t = threadIdx.x;

    for (int j = t; j < KKN * 16; j += 512) {
        int kk = j / 16, p = j % 16;
        int gi = (b * KKN + kk) * HWP + p0 + p;
        smw[kk][p] = g_mw[gi];
        smi[kk][p] = g_mi[gi];
    }
    __syncthreads();

    int pl = t >> 5;
    int ol = (t & 31) * 8;

    u64 a[4];
    {
        float4 b0 = *(const float4 *)(bdcn + ol);
        float4 b1 = *(const float4 *)(bdcn + ol + 4);
        a[0] = pack2(b0.x, b0.y); a[1] = pack2(b0.z, b0.w);
        a[2] = pack2(b1.x, b1.y); a[3] = pack2(b1.z, b1.w);
    }

#define CORNER(W, OFFS) do { \
        u64 ww = pack2((W), (W)); \
        const ulonglong2 *v = (const ulonglong2 *)(yk + (OFFS) + ol); \
        ulonglong2 v0 = __ldg(v), v1 = __ldg(v + 1); \
        a[0] = ffma2(v0.x, ww, a[0]); a[1] = ffma2(v0.y, ww, a[1]); \
        a[2] = ffma2(v1.x, ww, a[2]); a[3] = ffma2(v1.y, ww, a[3]); \
    } while (0)

#pragma unroll 1
    for (int kk = 0; kk < KKN; kk++) {
        const float *yk = g_y + (size_t)(kk * BB + b) * HWP * COUT;
        float4 w = smw[kk][pl];
        int4 ii = smi[kk][pl];
        CORNER(w.x, ii.x);
        CORNER(w.y, ii.y);
        CORNER(w.z, ii.z);
        CORNER(w.w, ii.w);
    }
#undef CORNER

    float *sr = &st[pl][ol];
#pragma unroll
    for (int j = 0; j < 4; j++) {
        float lo, hi; unpack2(a[j], lo, hi);
        sr[2 * j] = lo; sr[2 * j + 1] = hi;
    }
    __syncthreads();
    for (int idx = t; idx < 4096; idx += 512) {
        int o = idx >> 4, p2 = idx & 15;
        out[((size_t)b * COUT + o) * HWP + p0 + p2] = st[p2][o];
    }
}

// ---------------- launch ----------------
extern "C" void kernel_launch(void *const *d_in, const int *in_sizes, int n_in,
                              void *d_out, int out_size) {
    const float *x = (const float *)d_in[0];
    const float *w_om = (const float *)d_in[1];
    const float *b_om = (const float *)d_in[2];
    const float *w_dcn = (const float *)d_in[3];
    const float *b_dcn = (const float *)d_in[4];
    float *out = (float *)d_out;

    static int smem_set = 0;
    if (!smem_set) {
        cudaFuncSetAttribute(k_gemm, cudaFuncAttributeMaxDynamicSharedMemorySize, SM_TOT);
        smem_set = 1;
    }

    dim3 tg(HWP / 32, CIN / 32, BB);
    k_transpose<<<tg, dim3(32, 8, 1)>>>(x);

    k_wsplit<<<(KKN * COUT * CIN + 255) / 256, 256>>>(w_dcn);

    k_om<<<dim3(16, BB, 2), 128>>>(x, w_om);

    k_meta<<<(BB * KKN * HWP + 255) / 256, 256>>>(b_om);

    k_gemm<<<dim3(KKN, 16, 32), 256, SM_TOT>>>();

    k_out<<<dim3(HWP / 16, BB), 512>>>(b_dcn, out);
}

// round 5
// speedup vs baseline: 2.6716x; 1.1720x over previous
#include <cuda_runtime.h>
#include <cuda_bf16.h>
#include <math.h>
#include <stdint.h>

#define BB 8
#define CIN 256
#define COUT 256
#define HH 64
#define WW 64
#define HWP 4096
#define KKN 9

typedef unsigned long long u64;

// ---------------- low-level helpers ----------------
__device__ __forceinline__ u64 pack2(float lo, float hi) {
    u64 r; asm("mov.b64 %0, {%1,%2};" : "=l"(r) : "f"(lo), "f"(hi)); return r;
}
__device__ __forceinline__ void unpack2(u64 v, float &lo, float &hi) {
    asm("mov.b64 {%0,%1}, %2;" : "=f"(lo), "=f"(hi) : "l"(v));
}
__device__ __forceinline__ u64 ffma2(u64 a, u64 b, u64 c) {
    u64 d; asm("fma.rn.f32x2 %0, %1, %2, %3;" : "=l"(d) : "l"(a), "l"(b), "l"(c)); return d;
}
__device__ __forceinline__ uint32_t smem_u32(const void *p) {
    uint32_t a; asm("{ .reg .u64 t; cvta.to.shared.u64 t, %1; cvt.u32.u64 %0, t; }" : "=r"(a) : "l"(p));
    return a;
}

#define CP_ASYNC16(dst, src) \
    asm volatile("cp.async.cg.shared.global [%0], [%1], 16;" :: "r"(dst), "l"(src) : "memory")
#define CP_COMMIT() asm volatile("cp.async.commit_group;" ::: "memory")
#define CP_WAIT1() asm volatile("cp.async.wait_group 1;" ::: "memory")
#define CP_WAIT0() asm volatile("cp.async.wait_group 0;" ::: "memory")

#define LDSM_X4(r, addr) \
    asm volatile("ldmatrix.sync.aligned.m8n8.x4.shared.b16 {%0,%1,%2,%3}, [%4];" \
        : "=r"((r)[0]), "=r"((r)[1]), "=r"((r)[2]), "=r"((r)[3]) : "r"(addr))
#define LDSM_X2(r, addr) \
    asm volatile("ldmatrix.sync.aligned.m8n8.x2.shared.b16 {%0,%1}, [%2];" \
        : "=r"((r)[0]), "=r"((r)[1]) : "r"(addr))

#define MMA_BF16(d, a, b) \
    asm volatile("mma.sync.aligned.m16n8k16.row.col.f32.bf16.bf16.f32 " \
        "{%0,%1,%2,%3}, {%4,%5,%6,%7}, {%8,%9}, {%0,%1,%2,%3};" \
        : "+f"((d)[0]), "+f"((d)[1]), "+f"((d)[2]), "+f"((d)[3]) \
        : "r"((a)[0]), "r"((a)[1]), "r"((a)[2]), "r"((a)[3]), "r"((b)[0]), "r"((b)[1]))

#define SWZ(o) ((o) ^ (((o) >> 3) & 0x70))

// ---------------- scratch ----------------
__device__ __nv_bfloat16 g_xh[(size_t)BB * HWP * CIN];   // [b][p][c] hi
__device__ __nv_bfloat16 g_xl[(size_t)BB * HWP * CIN];   // lo
__device__ __nv_bfloat16 g_wh[KKN * COUT * CIN];         // [kk][o][c]
__device__ __nv_bfloat16 g_wl[KKN * COUT * CIN];
__device__ float  g_y[(size_t)KKN * BB * HWP * COUT];    // [kk][b][p][o]
__device__ float  g_ompart[4][BB * 27 * HWP];            // 4 c-splits of 64
__device__ float4 g_mw[BB * KKN * HWP];
__device__ int4   g_mi[BB * KKN * HWP];

// ================= 1) unified prep: om-conv + transpose/split + wsplit ============
// grid layout: [0,128) om | [128, 8320) transpose | [8320, 8464) wsplit
#define NB_OM 128
#define NB_TR 8192
#define NB_WS 144
#define NB_PREP (NB_OM + NB_TR + NB_WS)

__global__ void __launch_bounds__(256) k_prep(const float *__restrict__ x,
                                              const float *__restrict__ wom,
                                              const float *__restrict__ wdcn) {
    __shared__ __align__(16) char psm[16 * 243 * 8];   // 31104 B (om weights / transpose tile)
    int blk = blockIdx.x;
    int t = threadIdx.x;

    if (blk < NB_OM) {
        // -------- om conv: 27ch 3x3, 4 pixels/thread (two f32x2 pairs), c-split 4 ----
        int split = blk & 3;
        int b = (blk >> 2) & 7;
        int rb = blk >> 5;            // 0..3, 16 rows each
        int s = t >> 6;               // strip 0..3 (4 rows each)
        int ox = t & 63;
        int y0 = rb * 16 + s * 4;

        u64 acc0[27], acc1[27];
#pragma unroll
        for (int i = 0; i < 27; i++) { acc0[i] = 0ULL; acc1[i] = 0ULL; }

        bool rowok[6]; int rowoff[6];
#pragma unroll
        for (int r = 0; r < 6; r++) {
            int y = y0 - 1 + r;
            rowok[r] = (y >= 0) && (y < HH);
            rowoff[r] = rowok[r] ? y * WW : 0;
        }
        bool colok[3]; int coloff[3];
#pragma unroll
        for (int c = 0; c < 3; c++) {
            int xx = ox - 1 + c;
            colok[c] = (xx >= 0) && (xx < WW);
            coloff[c] = colok[c] ? xx : 0;
        }

        int cbase = split * 64;
        const float *xb = x + (size_t)b * CIN * HWP;
        u64 *wshf = (u64 *)psm;

        for (int cc = 0; cc < 64; cc += 16) {
            __syncthreads();
            for (int j = t; j < 16 * 243; j += 256) {
                int oc = j / 144, rem = j % 144;
                float g = wom[(size_t)oc * 2304 + (size_t)(cbase + cc) * 9 + rem];
                wshf[(rem / 9) * 243 + oc * 9 + (rem % 9)] = pack2(g, g);
            }
            __syncthreads();
#pragma unroll 1
            for (int cil = 0; cil < 16; cil++) {
                const float *xc = xb + (size_t)(cbase + cc + cil) * HWP;
                float a[6][3];
#pragma unroll
                for (int r = 0; r < 6; r++)
#pragma unroll
                    for (int c = 0; c < 3; c++)
                        a[r][c] = (rowok[r] && colok[c]) ? __ldg(xc + rowoff[r] + coloff[c]) : 0.f;
                u64 pv0[9], pv1[9];
#pragma unroll
                for (int kk = 0; kk < 9; kk++) {
                    int ki = kk / 3, kj = kk % 3;
                    pv0[kk] = pack2(a[ki][kj], a[ki + 2][kj]);
                    pv1[kk] = pack2(a[ki + 1][kj], a[ki + 3][kj]);
                }
                const u64 *wrow = &wshf[cil * 243];
#pragma unroll
                for (int kk = 0; kk < 9; kk++)
#pragma unroll
                    for (int oc = 0; oc < 27; oc++) {
                        u64 w = wrow[oc * 9 + kk];
                        acc0[oc] = ffma2(pv0[kk], w, acc0[oc]);
                        acc1[oc] = ffma2(pv1[kk], w, acc1[oc]);
                    }
            }
        }

        float *dst = &g_ompart[split][(size_t)b * 27 * HWP];
#pragma unroll
        for (int oc = 0; oc < 27; oc++) {
            float l0, h0, l1, h1;
            unpack2(acc0[oc], l0, h0);
            unpack2(acc1[oc], l1, h1);
            size_t base = (size_t)oc * HWP + y0 * WW + ox;
            dst[base] = l0;
            dst[base + WW] = l1;
            dst[base + 2 * WW] = h0;
            dst[base + 3 * WW] = h1;
        }
    } else if (blk < NB_OM + NB_TR) {
        // -------- NCHW -> NHWC transpose + bf16 split --------
        int n = blk - NB_OM;
        int p0 = (n & 127) * 32;
        int c0 = ((n >> 7) & 7) * 32;
        int b = n >> 10;
        float (*tile)[33] = (float (*)[33])psm;
        int tx = t & 31, ty = t >> 5;
        const float *src = x + (size_t)b * CIN * HWP;
#pragma unroll
        for (int k = 0; k < 32; k += 8)
            tile[ty + k][tx] = src[(size_t)(c0 + ty + k) * HWP + p0 + tx];
        __syncthreads();
        __nv_bfloat16 *dh = g_xh + (size_t)b * HWP * CIN;
        __nv_bfloat16 *dl = g_xl + (size_t)b * HWP * CIN;
#pragma unroll
        for (int k = 0; k < 32; k += 8) {
            float v = tile[tx][ty + k];
            __nv_bfloat16 h = __float2bfloat16(v);
            size_t idx = (size_t)(p0 + ty + k) * CIN + c0 + tx;
            dh[idx] = h;
            dl[idx] = __float2bfloat16(v - __bfloat162float(h));
        }
    } else {
        // -------- w_dcn -> [kk][o][c] bf16 split, 16 elems/thread --------
        int blkL = blk - (NB_OM + NB_TR);
        int base = blkL * 4096 + t;
#pragma unroll
        for (int k = 0; k < 16; k++) {
            int i = base + k * 256;
            int c = i % CIN;
            int o = (i / CIN) % COUT;
            int kk = i / (CIN * COUT);
            float v = wdcn[(size_t)(o * CIN + c) * KKN + kk];
            __nv_bfloat16 h = __float2bfloat16(v);
            g_wh[i] = h;
            g_wl[i] = __float2bfloat16(v - __bfloat162float(h));
        }
    }
}

// ---------------- 2) sampling metadata ----------------
__global__ void k_meta(const float *__restrict__ bom) {
    int i = blockIdx.x * 256 + threadIdx.x;
    if (i >= BB * KKN * HWP) return;
    int p = i % HWP;
    int t = i / HWP;
    int kk = t % KKN;
    int b = t / KKN;
    int oy = p >> 6, ox = p & 63;
    size_t ob = (size_t)b * 27 * HWP;
#define OMSUM(ch) (g_ompart[0][ob + (size_t)(ch) * HWP + p] + g_ompart[1][ob + (size_t)(ch) * HWP + p] + \
                   g_ompart[2][ob + (size_t)(ch) * HWP + p] + g_ompart[3][ob + (size_t)(ch) * HWP + p])
    float dy = OMSUM(kk) + bom[kk];
    float dx = OMSUM(9 + kk) + bom[9 + kk];
    float mz = OMSUM(18 + kk) + bom[18 + kk];
#undef OMSUM
    float m = 1.f / (1.f + expf(-mz));
    int ki = kk / 3, kj = kk % 3;
    float py = (float)(oy - 1 + ki) + dy;
    float px = (float)(ox - 1 + kj) + dx;
    float y0f = floorf(py), x0f = floorf(px);
    float ly = py - y0f, lx = px - x0f;
    int y0 = (int)y0f, x0 = (int)x0f;
    int y1 = y0 + 1, x1 = x0 + 1;

    float v00 = (y0 >= 0 && y0 < HH && x0 >= 0 && x0 < WW) ? 1.f : 0.f;
    float v01 = (y0 >= 0 && y0 < HH && x1 >= 0 && x1 < WW) ? 1.f : 0.f;
    float v10 = (y1 >= 0 && y1 < HH && x0 >= 0 && x0 < WW) ? 1.f : 0.f;
    float v11 = (y1 >= 0 && y1 < HH && x1 >= 0 && x1 < WW) ? 1.f : 0.f;
    int cy0 = min(max(y0, 0), HH - 1), cy1 = min(max(y1, 0), HH - 1);
    int cx0 = min(max(x0, 0), WW - 1), cx1 = min(max(x1, 0), WW - 1);

    g_mw[i] = make_float4((1.f - ly) * (1.f - lx) * m * v00,
                          (1.f - ly) * lx * m * v01,
                          ly * (1.f - lx) * m * v10,
                          ly * lx * m * v11);
    g_mi[i] = make_int4((cy0 * WW + cx0) * COUT, (cy0 * WW + cx1) * COUT,
                        (cy1 * WW + cx0) * COUT, (cy1 * WW + cx1) * COUT);
}

// ---------------- 3) persistent dense GEMMs via mma.sync bf16 2-way split -------
// tiles: NT = 9kk x 16(b,oh) x 32(ptile); tile = 128p x 128o, K=256 in 4 chunks of 64.
#define NT 4608
#define NSM 148
#define KC 64
#define STAGE_BYTES 65536
#define XH_OFF 0
#define XL_OFF 16384
#define WH_OFF 32768
#define WL_OFF 49152
#define SM_TOT (2 * STAGE_BYTES)

struct TileInfo {
    const __nv_bfloat16 *xh, *xl, *wh, *wl;
    size_t yoff;
};
__device__ __forceinline__ TileInfo tile_decode(int ti) {
    int inner = ti % 18;
    int outer = ti / 18;
    int b = outer >> 5;
    int p0 = (outer & 31) * 128;
    int kk = inner >> 1;
    int o0 = (inner & 1) * 128;
    TileInfo r;
    r.xh = g_xh + ((size_t)b * HWP + p0) * CIN;
    r.xl = g_xl + ((size_t)b * HWP + p0) * CIN;
    r.wh = g_wh + ((size_t)kk * COUT + o0) * CIN;
    r.wl = g_wl + ((size_t)kk * COUT + o0) * CIN;
    r.yoff = (((size_t)(kk * BB + b) * HWP + p0) * COUT) + o0;
    return r;
}

__global__ void __launch_bounds__(256, 1) k_gemm() {
    extern __shared__ char smem[];
    uint32_t sb = smem_u32(smem);
    int tid = threadIdx.x;
    int wid = tid >> 5, lane = tid & 31;
    int bid = blockIdx.x;

    int ntiles = (NT - bid + NSM - 1) / NSM;
    int NC = ntiles * 4;

    // per-thread load slots
    int lsw4[4], lrow4[4], latom4[4];
#pragma unroll
    for (int k2 = 0; k2 < 4; k2++) {
        int idx = tid + k2 * 256;
        lrow4[k2] = idx >> 3;
        latom4[k2] = idx & 7;
        lsw4[k2] = SWZ((idx >> 3) * 128 + (idx & 7) * 16);
    }

#define ISSUE_CHUNK(n) do { \
        int _ti = bid + ((n) >> 2) * NSM; \
        TileInfo _t = tile_decode(_ti); \
        int _c0 = ((n) & 3) * KC; \
        uint32_t _stb = sb + ((n) & 1) * STAGE_BYTES; \
        _Pragma("unroll") \
        for (int k2 = 0; k2 < 4; k2++) { \
            size_t g = (size_t)lrow4[k2] * CIN + _c0 + latom4[k2] * 8; \
            CP_ASYNC16(_stb + XH_OFF + lsw4[k2], _t.xh + g); \
            CP_ASYNC16(_stb + XL_OFF + lsw4[k2], _t.xl + g); \
            CP_ASYNC16(_stb + WH_OFF + lsw4[k2], _t.wh + g); \
            CP_ASYNC16(_stb + WL_OFF + lsw4[k2], _t.wl + g); \
        } \
    } while (0)

    int wp = wid >> 2;          // 0..1  (64 p rows)
    int wo = wid & 3;           // 0..3  (32 o cols)
    int abase = (wp * 64 + (lane & 15)) * 128 + ((lane >> 4) * 8) * 2;
    int bbase = (wo * 32 + (lane & 7)) * 128 + (((lane >> 3) & 1) * 8) * 2;

    float d[4][4][4];
#pragma unroll
    for (int mt = 0; mt < 4; mt++)
#pragma unroll
        for (int nt = 0; nt < 4; nt++)
#pragma unroll
            for (int j = 0; j < 4; j++) d[mt][nt][j] = 0.f;

    // prologue: chunks 0 and 1
    ISSUE_CHUNK(0); CP_COMMIT();
    if (NC > 1) ISSUE_CHUNK(1);
    CP_COMMIT();

    for (int n = 0; n < NC; n++) {
        if (n + 1 < NC) { CP_WAIT1(); } else { CP_WAIT0(); }
        __syncthreads();

        uint32_t stb = sb + (n & 1) * STAGE_BYTES;
#pragma unroll
        for (int ks = 0; ks < 4; ks++) {
            uint32_t ah[4][4], al[4][4];
#pragma unroll
            for (int mt = 0; mt < 4; mt++) {
                int off = abase + mt * 2048 + ks * 32;
                LDSM_X4(ah[mt], stb + XH_OFF + SWZ(off));
                LDSM_X4(al[mt], stb + XL_OFF + SWZ(off));
            }
            uint32_t bh[4][2], bl[4][2];
#pragma unroll
            for (int nt = 0; nt < 4; nt++) {
                int off = bbase + nt * 1024 + ks * 32;
                LDSM_X2(bh[nt], stb + WH_OFF + SWZ(off));
                LDSM_X2(bl[nt], stb + WL_OFF + SWZ(off));
            }
#pragma unroll
            for (int mt = 0; mt < 4; mt++)
#pragma unroll
                for (int nt = 0; nt < 4; nt++) {
                    MMA_BF16(d[mt][nt], ah[mt], bh[nt]);
                    MMA_BF16(d[mt][nt], ah[mt], bl[nt]);
                    MMA_BF16(d[mt][nt], al[mt], bh[nt]);
                }
        }
        __syncthreads();   // all warps done reading this stage before overwrite

        if (n + 2 < NC) ISSUE_CHUNK(n + 2);
        CP_COMMIT();       // always commit (possibly empty) to keep group count aligned

        if ((n & 3) == 3) {
            // epilogue: direct STG.64 from fragments (smem stays free for prefetch)
            int ti = bid + (n >> 2) * NSM;
            TileInfo tinfo = tile_decode(ti);
            float *yo = g_y + tinfo.yoff;
#pragma unroll
            for (int mt = 0; mt < 4; mt++) {
                int r0 = wp * 64 + mt * 16 + (lane >> 2);
#pragma unroll
                for (int nt = 0; nt < 4; nt++) {
                    int c = wo * 32 + nt * 8 + (lane & 3) * 2;
                    *(float2 *)(yo + (size_t)r0 * COUT + c) = make_float2(d[mt][nt][0], d[mt][nt][1]);
                    *(float2 *)(yo + (size_t)(r0 + 8) * COUT + c) = make_float2(d[mt][nt][2], d[mt][nt][3]);
                    d[mt][nt][0] = 0.f; d[mt][nt][1] = 0.f; d[mt][nt][2] = 0.f; d[mt][nt][3] = 0.f;
                }
            }
        }
    }
#undef ISSUE_CHUNK
}

// ---------------- 4) gather-axpy assembly: out[b][o][p] ----------------
__global__ void __launch_bounds__(512) k_out(const float *__restrict__ bdcn,
                                             float *__restrict__ out) {
    __shared__ float4 smw[KKN][16];
    __shared__ int4 smi[KKN][16];
    __shared__ float st[16][257];
    int b = blockIdx.y;
    int p0 = blockIdx.x * 16;
    int t = threadIdx.x;

    for (int j = t; j < KKN * 16; j += 512) {
        int kk = j / 16, p = j % 16;
        int gi = (b * KKN + kk) * HWP + p0 + p;
        smw[kk][p] = g_mw[gi];
        smi[kk][p] = g_mi[gi];
    }
    __syncthreads();

    int pl = t >> 5;
    int ol = (t & 31) * 8;

    u64 a[4];
    {
        float4 b0 = *(const float4 *)(bdcn + ol);
        float4 b1 = *(const float4 *)(bdcn + ol + 4);
        a[0] = pack2(b0.x, b0.y); a[1] = pack2(b0.z, b0.w);
        a[2] = pack2(b1.x, b1.y); a[3] = pack2(b1.z, b1.w);
    }

#define CORNER(W, OFFS) do { \
        u64 ww = pack2((W), (W)); \
        const ulonglong2 *v = (const ulonglong2 *)(yk + (OFFS) + ol); \
        ulonglong2 v0 = __ldg(v), v1 = __ldg(v + 1); \
        a[0] = ffma2(v0.x, ww, a[0]); a[1] = ffma2(v0.y, ww, a[1]); \
        a[2] = ffma2(v1.x, ww, a[2]); a[3] = ffma2(v1.y, ww, a[3]); \
    } while (0)

#pragma unroll 1
    for (int kk = 0; kk < KKN; kk++) {
        const float *yk = g_y + (size_t)(kk * BB + b) * HWP * COUT;
        float4 w = smw[kk][pl];
        int4 ii = smi[kk][pl];
        CORNER(w.x, ii.x);
        CORNER(w.y, ii.y);
        CORNER(w.z, ii.z);
        CORNER(w.w, ii.w);
    }
#undef CORNER

    float *sr = &st[pl][ol];
#pragma unroll
    for (int j = 0; j < 4; j++) {
        float lo, hi; unpack2(a[j], lo, hi);
        sr[2 * j] = lo; sr[2 * j + 1] = hi;
    }
    __syncthreads();
    for (int idx = t; idx < 4096; idx += 512) {
        int o = idx >> 4, p2 = idx & 15;
        out[((size_t)b * COUT + o) * HWP + p0 + p2] = st[p2][o];
    }
}

// ---------------- launch ----------------
extern "C" void kernel_launch(void *const *d_in, const int *in_sizes, int n_in,
                              void *d_out, int out_size) {
    const float *x = (const float *)d_in[0];
    const float *w_om = (const float *)d_in[1];
    const float *b_om = (const float *)d_in[2];
    const float *w_dcn = (const float *)d_in[3];
    const float *b_dcn = (const float *)d_in[4];
    float *out = (float *)d_out;

    static int smem_set = 0;
    if (!smem_set) {
        cudaFuncSetAttribute(k_gemm, cudaFuncAttributeMaxDynamicSharedMemorySize, SM_TOT);
        smem_set = 1;
    }

    k_prep<<<NB_PREP, 256>>>(x, w_om, w_dcn);

    k_meta<<<(BB * KKN * HWP + 255) / 256, 256>>>(b_om);

    k_gemm<<<NSM, 256, SM_TOT>>>();

    k_out<<<dim3(HWP / 16, BB), 512>>>(b_dcn, out);
}

// round 6
// speedup vs baseline: 2.8198x; 1.0555x over previous
#include <cuda_runtime.h>
#include <cuda_bf16.h>
#include <cuda_fp16.h>
#include <math.h>
#include <stdint.h>

#define BB 8
#define CIN 256
#define COUT 256
#define HH 64
#define WW 64
#define HWP 4096
#define KKN 9

typedef unsigned long long u64;

// ---------------- low-level helpers ----------------
__device__ __forceinline__ u64 pack2(float lo, float hi) {
    u64 r; asm("mov.b64 %0, {%1,%2};" : "=l"(r) : "f"(lo), "f"(hi)); return r;
}
__device__ __forceinline__ void unpack2(u64 v, float &lo, float &hi) {
    asm("mov.b64 {%0,%1}, %2;" : "=f"(lo), "=f"(hi) : "l"(v));
}
__device__ __forceinline__ u64 ffma2(u64 a, u64 b, u64 c) {
    u64 d; asm("fma.rn.f32x2 %0, %1, %2, %3;" : "=l"(d) : "l"(a), "l"(b), "l"(c)); return d;
}
__device__ __forceinline__ uint32_t smem_u32(const void *p) {
    uint32_t a; asm("{ .reg .u64 t; cvta.to.shared.u64 t, %1; cvt.u32.u64 %0, t; }" : "=r"(a) : "l"(p));
    return a;
}

#define CP_ASYNC16(dst, src) \
    asm volatile("cp.async.cg.shared.global [%0], [%1], 16;" :: "r"(dst), "l"(src) : "memory")
#define CP_COMMIT() asm volatile("cp.async.commit_group;" ::: "memory")
#define CP_WAIT1() asm volatile("cp.async.wait_group 1;" ::: "memory")
#define CP_WAIT0() asm volatile("cp.async.wait_group 0;" ::: "memory")

#define LDSM_X4(r, addr) \
    asm volatile("ldmatrix.sync.aligned.m8n8.x4.shared.b16 {%0,%1,%2,%3}, [%4];" \
        : "=r"((r)[0]), "=r"((r)[1]), "=r"((r)[2]), "=r"((r)[3]) : "r"(addr))
#define LDSM_X2(r, addr) \
    asm volatile("ldmatrix.sync.aligned.m8n8.x2.shared.b16 {%0,%1}, [%2];" \
        : "=r"((r)[0]), "=r"((r)[1]) : "r"(addr))

#define MMA_BF16(d, a, b) \
    asm volatile("mma.sync.aligned.m16n8k16.row.col.f32.bf16.bf16.f32 " \
        "{%0,%1,%2,%3}, {%4,%5,%6,%7}, {%8,%9}, {%0,%1,%2,%3};" \
        : "+f"((d)[0]), "+f"((d)[1]), "+f"((d)[2]), "+f"((d)[3]) \
        : "r"((a)[0]), "r"((a)[1]), "r"((a)[2]), "r"((a)[3]), "r"((b)[0]), "r"((b)[1]))

#define SWZ(o) ((o) ^ (((o) >> 3) & 0x70))

// ---------------- scratch ----------------
__device__ __nv_bfloat16 g_xh[(size_t)BB * HWP * CIN];   // [b][p][c] hi
__device__ __nv_bfloat16 g_xl[(size_t)BB * HWP * CIN];   // lo
__device__ __nv_bfloat16 g_wh[KKN * COUT * CIN];         // [kk][o][c]
__device__ __nv_bfloat16 g_wl[KKN * COUT * CIN];
__device__ __half g_y[(size_t)KKN * BB * HWP * COUT];    // [kk][b][p][o] fp16
__device__ float  g_ompart[4][BB * 27 * HWP];            // 4 c-splits of 64
__device__ float4 g_mw[BB * KKN * HWP];
__device__ int4   g_mi[BB * KKN * HWP];

// ================= 1) unified prep: om-conv + transpose/split + wsplit ============
#define NB_OM 128
#define NB_TR 8192
#define NB_WS 144
#define NB_PREP (NB_OM + NB_TR + NB_WS)

__global__ void __launch_bounds__(256) k_prep(const float *__restrict__ x,
                                              const float *__restrict__ wom,
                                              const float *__restrict__ wdcn) {
    __shared__ __align__(16) char psm[16 * 243 * 8];   // 31104 B
    int blk = blockIdx.x;
    int t = threadIdx.x;

    if (blk < NB_OM) {
        // -------- om conv: 27ch 3x3, 4 pixels/thread, c-split 4 ----
        int split = blk & 3;
        int b = (blk >> 2) & 7;
        int rb = blk >> 5;
        int s = t >> 6;
        int ox = t & 63;
        int y0 = rb * 16 + s * 4;

        u64 acc0[27], acc1[27];
#pragma unroll
        for (int i = 0; i < 27; i++) { acc0[i] = 0ULL; acc1[i] = 0ULL; }

        bool rowok[6]; int rowoff[6];
#pragma unroll
        for (int r = 0; r < 6; r++) {
            int y = y0 - 1 + r;
            rowok[r] = (y >= 0) && (y < HH);
            rowoff[r] = rowok[r] ? y * WW : 0;
        }
        bool colok[3]; int coloff[3];
#pragma unroll
        for (int c = 0; c < 3; c++) {
            int xx = ox - 1 + c;
            colok[c] = (xx >= 0) && (xx < WW);
            coloff[c] = colok[c] ? xx : 0;
        }

        int cbase = split * 64;
        const float *xb = x + (size_t)b * CIN * HWP;
        u64 *wshf = (u64 *)psm;

        for (int cc = 0; cc < 64; cc += 16) {
            __syncthreads();
            for (int j = t; j < 16 * 243; j += 256) {
                int oc = j / 144, rem = j % 144;
                float g = wom[(size_t)oc * 2304 + (size_t)(cbase + cc) * 9 + rem];
                wshf[(rem / 9) * 243 + oc * 9 + (rem % 9)] = pack2(g, g);
            }
            __syncthreads();
#pragma unroll 1
            for (int cil = 0; cil < 16; cil++) {
                const float *xc = xb + (size_t)(cbase + cc + cil) * HWP;
                float a[6][3];
#pragma unroll
                for (int r = 0; r < 6; r++)
#pragma unroll
                    for (int c = 0; c < 3; c++)
                        a[r][c] = (rowok[r] && colok[c]) ? __ldg(xc + rowoff[r] + coloff[c]) : 0.f;
                u64 pv0[9], pv1[9];
#pragma unroll
                for (int kk = 0; kk < 9; kk++) {
                    int ki = kk / 3, kj = kk % 3;
                    pv0[kk] = pack2(a[ki][kj], a[ki + 2][kj]);
                    pv1[kk] = pack2(a[ki + 1][kj], a[ki + 3][kj]);
                }
                const u64 *wrow = &wshf[cil * 243];
#pragma unroll
                for (int kk = 0; kk < 9; kk++)
#pragma unroll
                    for (int oc = 0; oc < 27; oc++) {
                        u64 w = wrow[oc * 9 + kk];
                        acc0[oc] = ffma2(pv0[kk], w, acc0[oc]);
                        acc1[oc] = ffma2(pv1[kk], w, acc1[oc]);
                    }
            }
        }

        float *dst = &g_ompart[split][(size_t)b * 27 * HWP];
#pragma unroll
        for (int oc = 0; oc < 27; oc++) {
            float l0, h0, l1, h1;
            unpack2(acc0[oc], l0, h0);
            unpack2(acc1[oc], l1, h1);
            size_t base = (size_t)oc * HWP + y0 * WW + ox;
            dst[base] = l0;
            dst[base + WW] = l1;
            dst[base + 2 * WW] = h0;
            dst[base + 3 * WW] = h1;
        }
    } else if (blk < NB_OM + NB_TR) {
        // -------- NCHW -> NHWC transpose + bf16 split --------
        int n = blk - NB_OM;
        int p0 = (n & 127) * 32;
        int c0 = ((n >> 7) & 7) * 32;
        int b = n >> 10;
        float (*tile)[33] = (float (*)[33])psm;
        int tx = t & 31, ty = t >> 5;
        const float *src = x + (size_t)b * CIN * HWP;
#pragma unroll
        for (int k = 0; k < 32; k += 8)
            tile[ty + k][tx] = src[(size_t)(c0 + ty + k) * HWP + p0 + tx];
        __syncthreads();
        __nv_bfloat16 *dh = g_xh + (size_t)b * HWP * CIN;
        __nv_bfloat16 *dl = g_xl + (size_t)b * HWP * CIN;
#pragma unroll
        for (int k = 0; k < 32; k += 8) {
            float v = tile[tx][ty + k];
            __nv_bfloat16 h = __float2bfloat16(v);
            size_t idx = (size_t)(p0 + ty + k) * CIN + c0 + tx;
            dh[idx] = h;
            dl[idx] = __float2bfloat16(v - __bfloat162float(h));
        }
    } else {
        // -------- w_dcn -> [kk][o][c] bf16 split --------
        int blkL = blk - (NB_OM + NB_TR);
        int base = blkL * 4096 + t;
#pragma unroll
        for (int k = 0; k < 16; k++) {
            int i = base + k * 256;
            int c = i % CIN;
            int o = (i / CIN) % COUT;
            int kk = i / (CIN * COUT);
            float v = wdcn[(size_t)(o * CIN + c) * KKN + kk];
            __nv_bfloat16 h = __float2bfloat16(v);
            g_wh[i] = h;
            g_wl[i] = __float2bfloat16(v - __bfloat162float(h));
        }
    }
}

// ---------------- 2) sampling metadata ----------------
__global__ void k_meta(const float *__restrict__ bom) {
    int i = blockIdx.x * 256 + threadIdx.x;
    if (i >= BB * KKN * HWP) return;
    int p = i % HWP;
    int t = i / HWP;
    int kk = t % KKN;
    int b = t / KKN;
    int oy = p >> 6, ox = p & 63;
    size_t ob = (size_t)b * 27 * HWP;
#define OMSUM(ch) (g_ompart[0][ob + (size_t)(ch) * HWP + p] + g_ompart[1][ob + (size_t)(ch) * HWP + p] + \
                   g_ompart[2][ob + (size_t)(ch) * HWP + p] + g_ompart[3][ob + (size_t)(ch) * HWP + p])
    float dy = OMSUM(kk) + bom[kk];
    float dx = OMSUM(9 + kk) + bom[9 + kk];
    float mz = OMSUM(18 + kk) + bom[18 + kk];
#undef OMSUM
    float m = 1.f / (1.f + expf(-mz));
    int ki = kk / 3, kj = kk % 3;
    float py = (float)(oy - 1 + ki) + dy;
    float px = (float)(ox - 1 + kj) + dx;
    float y0f = floorf(py), x0f = floorf(px);
    float ly = py - y0f, lx = px - x0f;
    int y0 = (int)y0f, x0 = (int)x0f;
    int y1 = y0 + 1, x1 = x0 + 1;

    float v00 = (y0 >= 0 && y0 < HH && x0 >= 0 && x0 < WW) ? 1.f : 0.f;
    float v01 = (y0 >= 0 && y0 < HH && x1 >= 0 && x1 < WW) ? 1.f : 0.f;
    float v10 = (y1 >= 0 && y1 < HH && x0 >= 0 && x0 < WW) ? 1.f : 0.f;
    float v11 = (y1 >= 0 && y1 < HH && x1 >= 0 && x1 < WW) ? 1.f : 0.f;
    int cy0 = min(max(y0, 0), HH - 1), cy1 = min(max(y1, 0), HH - 1);
    int cx0 = min(max(x0, 0), WW - 1), cx1 = min(max(x1, 0), WW - 1);

    g_mw[i] = make_float4((1.f - ly) * (1.f - lx) * m * v00,
                          (1.f - ly) * lx * m * v01,
                          ly * (1.f - lx) * m * v10,
                          ly * lx * m * v11);
    g_mi[i] = make_int4((cy0 * WW + cx0) * COUT, (cy0 * WW + cx1) * COUT,
                        (cy1 * WW + cx0) * COUT, (cy1 * WW + cx1) * COUT);
}

// ---------------- 3) persistent dense GEMMs via mma.sync bf16 2-way split -------
#define NT 4608
#define NSM 148
#define KC 64
#define STAGE_BYTES 65536
#define XH_OFF 0
#define XL_OFF 16384
#define WH_OFF 32768
#define WL_OFF 49152
#define SM_TOT (2 * STAGE_BYTES)

struct TileInfo {
    const __nv_bfloat16 *xh, *xl, *wh, *wl;
    size_t yoff;
};
__device__ __forceinline__ TileInfo tile_decode(int ti) {
    int inner = ti % 18;
    int outer = ti / 18;
    int b = outer >> 5;
    int p0 = (outer & 31) * 128;
    int kk = inner >> 1;
    int o0 = (inner & 1) * 128;
    TileInfo r;
    r.xh = g_xh + ((size_t)b * HWP + p0) * CIN;
    r.xl = g_xl + ((size_t)b * HWP + p0) * CIN;
    r.wh = g_wh + ((size_t)kk * COUT + o0) * CIN;
    r.wl = g_wl + ((size_t)kk * COUT + o0) * CIN;
    r.yoff = (((size_t)(kk * BB + b) * HWP + p0) * COUT) + o0;
    return r;
}

__global__ void __launch_bounds__(256, 1) k_gemm() {
    extern __shared__ char smem[];
    uint32_t sb = smem_u32(smem);
    int tid = threadIdx.x;
    int wid = tid >> 5, lane = tid & 31;
    int bid = blockIdx.x;

    int ntiles = (NT - bid + NSM - 1) / NSM;
    int NC = ntiles * 4;

    int lsw4[4], lrow4[4], latom4[4];
#pragma unroll
    for (int k2 = 0; k2 < 4; k2++) {
        int idx = tid + k2 * 256;
        lrow4[k2] = idx >> 3;
        latom4[k2] = idx & 7;
        lsw4[k2] = SWZ((idx >> 3) * 128 + (idx & 7) * 16);
    }

#define ISSUE_CHUNK(n) do { \
        int _ti = bid + ((n) >> 2) * NSM; \
        TileInfo _t = tile_decode(_ti); \
        int _c0 = ((n) & 3) * KC; \
        uint32_t _stb = sb + ((n) & 1) * STAGE_BYTES; \
        _Pragma("unroll") \
        for (int k2 = 0; k2 < 4; k2++) { \
            size_t g = (size_t)lrow4[k2] * CIN + _c0 + latom4[k2] * 8; \
            CP_ASYNC16(_stb + XH_OFF + lsw4[k2], _t.xh + g); \
            CP_ASYNC16(_stb + XL_OFF + lsw4[k2], _t.xl + g); \
            CP_ASYNC16(_stb + WH_OFF + lsw4[k2], _t.wh + g); \
            CP_ASYNC16(_stb + WL_OFF + lsw4[k2], _t.wl + g); \
        } \
    } while (0)

    int wp = wid >> 2;
    int wo = wid & 3;
    int abase = (wp * 64 + (lane & 15)) * 128 + ((lane >> 4) * 8) * 2;
    int bbase = (wo * 32 + (lane & 7)) * 128 + (((lane >> 3) & 1) * 8) * 2;

    float d[4][4][4];
#pragma unroll
    for (int mt = 0; mt < 4; mt++)
#pragma unroll
        for (int nt = 0; nt < 4; nt++)
#pragma unroll
            for (int j = 0; j < 4; j++) d[mt][nt][j] = 0.f;

    ISSUE_CHUNK(0); CP_COMMIT();
    if (NC > 1) ISSUE_CHUNK(1);
    CP_COMMIT();

    for (int n = 0; n < NC; n++) {
        if (n + 1 < NC) { CP_WAIT1(); } else { CP_WAIT0(); }
        __syncthreads();

        uint32_t stb = sb + (n & 1) * STAGE_BYTES;
#pragma unroll
        for (int ks = 0; ks < 4; ks++) {
            uint32_t ah[4][4], al[4][4];
#pragma unroll
            for (int mt = 0; mt < 4; mt++) {
                int off = abase + mt * 2048 + ks * 32;
                LDSM_X4(ah[mt], stb + XH_OFF + SWZ(off));
                LDSM_X4(al[mt], stb + XL_OFF + SWZ(off));
            }
            uint32_t bh[4][2], bl[4][2];
#pragma unroll
            for (int nt = 0; nt < 4; nt++) {
                int off = bbase + nt * 1024 + ks * 32;
                LDSM_X2(bh[nt], stb + WH_OFF + SWZ(off));
                LDSM_X2(bl[nt], stb + WL_OFF + SWZ(off));
            }
#pragma unroll
            for (int mt = 0; mt < 4; mt++)
#pragma unroll
                for (int nt = 0; nt < 4; nt++) {
                    MMA_BF16(d[mt][nt], ah[mt], bh[nt]);
                    MMA_BF16(d[mt][nt], ah[mt], bl[nt]);
                    MMA_BF16(d[mt][nt], al[mt], bh[nt]);
                }
        }
        __syncthreads();

        if (n + 2 < NC) ISSUE_CHUNK(n + 2);
        CP_COMMIT();

        if ((n & 3) == 3) {
            // epilogue: fp32 fragments -> half2 STG.32 (half the write traffic)
            int ti = bid + (n >> 2) * NSM;
            TileInfo tinfo = tile_decode(ti);
            __half *yo = g_y + tinfo.yoff;
#pragma unroll
            for (int mt = 0; mt < 4; mt++) {
                int r0 = wp * 64 + mt * 16 + (lane >> 2);
#pragma unroll
                for (int nt = 0; nt < 4; nt++) {
                    int c = wo * 32 + nt * 8 + (lane & 3) * 2;
                    *(__half2 *)(yo + (size_t)r0 * COUT + c) = __floats2half2_rn(d[mt][nt][0], d[mt][nt][1]);
                    *(__half2 *)(yo + (size_t)(r0 + 8) * COUT + c) = __floats2half2_rn(d[mt][nt][2], d[mt][nt][3]);
                    d[mt][nt][0] = 0.f; d[mt][nt][1] = 0.f; d[mt][nt][2] = 0.f; d[mt][nt][3] = 0.f;
                }
            }
        }
    }
#undef ISSUE_CHUNK
}

// ---------------- 4) gather-axpy assembly: out[b][o][p] ----------------
__global__ void __launch_bounds__(512) k_out(const float *__restrict__ bdcn,
                                             float *__restrict__ out) {
    __shared__ float4 smw[KKN][16];
    __shared__ int4 smi[KKN][16];
    __shared__ float st[16][257];
    int b = blockIdx.y;
    int p0 = blockIdx.x * 16;
    int t = threadIdx.x;

    for (int j = t; j < KKN * 16; j += 512) {
        int kk = j / 16, p = j % 16;
        int gi = (b * KKN + kk) * HWP + p0 + p;
        smw[kk][p] = g_mw[gi];
        smi[kk][p] = g_mi[gi];
    }
    __syncthreads();

    int pl = t >> 5;
    int ol = (t & 31) * 8;

    u64 a[4];
    {
        float4 b0 = *(const float4 *)(bdcn + ol);
        float4 b1 = *(const float4 *)(bdcn + ol + 4);
        a[0] = pack2(b0.x, b0.y); a[1] = pack2(b0.z, b0.w);
        a[2] = pack2(b1.x, b1.y); a[3] = pack2(b1.z, b1.w);
    }

    // one LDG.128 fetches 8 halfs (all this thread's o-values) per corner
#define CORNER(W, OFFS) do { \
        u64 ww = pack2((W), (W)); \
        uint4 v = __ldg((const uint4 *)(yk + (OFFS) + ol)); \
        const __half2 *hp = (const __half2 *)&v; \
        _Pragma("unroll") \
        for (int j = 0; j < 4; j++) { \
            float2 f = __half22float2(hp[j]); \
            a[j] = ffma2(pack2(f.x, f.y), ww, a[j]); \
        } \
    } while (0)

#pragma unroll 1
    for (int kk = 0; kk < KKN; kk++) {
        const __half *yk = g_y + (size_t)(kk * BB + b) * HWP * COUT;
        float4 w = smw[kk][pl];
        int4 ii = smi[kk][pl];
        CORNER(w.x, ii.x);
        CORNER(w.y, ii.y);
        CORNER(w.z, ii.z);
        CORNER(w.w, ii.w);
    }
#undef CORNER

    float *sr = &st[pl][ol];
#pragma unroll
    for (int j = 0; j < 4; j++) {
        float lo, hi; unpack2(a[j], lo, hi);
        sr[2 * j] = lo; sr[2 * j + 1] = hi;
    }
    __syncthreads();
    for (int idx = t; idx < 4096; idx += 512) {
        int o = idx >> 4, p2 = idx & 15;
        out[((size_t)b * COUT + o) * HWP + p0 + p2] = st[p2][o];
    }
}

// ---------------- launch ----------------
extern "C" void kernel_launch(void *const *d_in, const int *in_sizes, int n_in,
                              void *d_out, int out_size) {
    const float *x = (const float *)d_in[0];
    const float *w_om = (const float *)d_in[1];
    const float *b_om = (const float *)d_in[2];
    const float *w_dcn = (const float *)d_in[3];
    const float *b_dcn = (const float *)d_in[4];
    float *out = (float *)d_out;

    static int smem_set = 0;
    if (!smem_set) {
        cudaFuncSetAttribute(k_gemm, cudaFuncAttributeMaxDynamicSharedMemorySize, SM_TOT);
        smem_set = 1;
    }

    k_prep<<<NB_PREP, 256>>>(x, w_om, w_dcn);

    k_meta<<<(BB * KKN * HWP + 255) / 256, 256>>>(b_om);

    k_gemm<<<NSM, 256, SM_TOT>>>();

    k_out<<<dim3(HWP / 16, BB), 512>>>(b_dcn, out);
}

// round 7
// speedup vs baseline: 4.1892x; 1.4856x over previous
#include <cuda_runtime.h>
#include <cuda_fp16.h>
#include <math.h>
#include <stdint.h>

#define BB 8
#define CIN 256
#define COUT 256
#define HH 64
#define WW 64
#define HWP 4096
#define KKN 9

typedef unsigned long long u64;

// ---------------- low-level helpers ----------------
__device__ __forceinline__ u64 pack2(float lo, float hi) {
    u64 r; asm("mov.b64 %0, {%1,%2};" : "=l"(r) : "f"(lo), "f"(hi)); return r;
}
__device__ __forceinline__ void unpack2(u64 v, float &lo, float &hi) {
    asm("mov.b64 {%0,%1}, %2;" : "=f"(lo), "=f"(hi) : "l"(v));
}
__device__ __forceinline__ u64 ffma2(u64 a, u64 b, u64 c) {
    u64 d; asm("fma.rn.f32x2 %0, %1, %2, %3;" : "=l"(d) : "l"(a), "l"(b), "l"(c)); return d;
}
__device__ __forceinline__ uint32_t smem_u32(const void *p) {
    uint32_t a; asm("{ .reg .u64 t; cvta.to.shared.u64 t, %1; cvt.u32.u64 %0, t; }" : "=r"(a) : "l"(p));
    return a;
}

#define CP_ASYNC16(dst, src) \
    asm volatile("cp.async.cg.shared.global [%0], [%1], 16;" :: "r"(dst), "l"(src) : "memory")
#define CP_COMMIT() asm volatile("cp.async.commit_group;" ::: "memory")
#define CP_WAIT1() asm volatile("cp.async.wait_group 1;" ::: "memory")
#define CP_WAIT0() asm volatile("cp.async.wait_group 0;" ::: "memory")

#define LDSM_X4(r, addr) \
    asm volatile("ldmatrix.sync.aligned.m8n8.x4.shared.b16 {%0,%1,%2,%3}, [%4];" \
        : "=r"((r)[0]), "=r"((r)[1]), "=r"((r)[2]), "=r"((r)[3]) : "r"(addr))
#define LDSM_X2(r, addr) \
    asm volatile("ldmatrix.sync.aligned.m8n8.x2.shared.b16 {%0,%1}, [%2];" \
        : "=r"((r)[0]), "=r"((r)[1]) : "r"(addr))

#define MMA_FP16(d, a, b) \
    asm volatile("mma.sync.aligned.m16n8k16.row.col.f32.f16.f16.f32 " \
        "{%0,%1,%2,%3}, {%4,%5,%6,%7}, {%8,%9}, {%0,%1,%2,%3};" \
        : "+f"((d)[0]), "+f"((d)[1]), "+f"((d)[2]), "+f"((d)[3]) \
        : "r"((a)[0]), "r"((a)[1]), "r"((a)[2]), "r"((a)[3]), "r"((b)[0]), "r"((b)[1]))

#define SWZ(o) ((o) ^ (((o) >> 3) & 0x70))

// ---------------- scratch ----------------
__device__ __half g_xf[(size_t)BB * HWP * CIN];          // [b][p][c] fp16
__device__ __half g_wf[KKN * COUT * CIN];                // [kk][o][c] fp16
__device__ __half g_y[(size_t)KKN * BB * HWP * COUT];    // [kk][b][p][o] fp16
__device__ float  g_ompart[4][BB * 27 * HWP];            // 4 c-splits of 64
__device__ float4 g_mw[BB * KKN * HWP];
__device__ int4   g_mi[BB * KKN * HWP];

// ================= 1) unified prep: om-conv + transpose + wconv ============
#define NB_OM 128
#define NB_TR 8192
#define NB_WS 144
#define NB_PREP (NB_OM + NB_TR + NB_WS)

__global__ void __launch_bounds__(256) k_prep(const float *__restrict__ x,
                                              const float *__restrict__ wom,
                                              const float *__restrict__ wdcn) {
    __shared__ __align__(16) char psm[16 * 243 * 8];   // 31104 B
    int blk = blockIdx.x;
    int t = threadIdx.x;

    if (blk < NB_OM) {
        // -------- om conv: 27ch 3x3, 4 pixels/thread, c-split 4 ----
        int split = blk & 3;
        int b = (blk >> 2) & 7;
        int rb = blk >> 5;
        int s = t >> 6;
        int ox = t & 63;
        int y0 = rb * 16 + s * 4;

        u64 acc0[27], acc1[27];
#pragma unroll
        for (int i = 0; i < 27; i++) { acc0[i] = 0ULL; acc1[i] = 0ULL; }

        bool rowok[6]; int rowoff[6];
#pragma unroll
        for (int r = 0; r < 6; r++) {
            int y = y0 - 1 + r;
            rowok[r] = (y >= 0) && (y < HH);
            rowoff[r] = rowok[r] ? y * WW : 0;
        }
        bool colok[3]; int coloff[3];
#pragma unroll
        for (int c = 0; c < 3; c++) {
            int xx = ox - 1 + c;
            colok[c] = (xx >= 0) && (xx < WW);
            coloff[c] = colok[c] ? xx : 0;
        }

        int cbase = split * 64;
        const float *xb = x + (size_t)b * CIN * HWP;
        u64 *wshf = (u64 *)psm;

        for (int cc = 0; cc < 64; cc += 16) {
            __syncthreads();
            for (int j = t; j < 16 * 243; j += 256) {
                int oc = j / 144, rem = j % 144;
                float g = wom[(size_t)oc * 2304 + (size_t)(cbase + cc) * 9 + rem];
                wshf[(rem / 9) * 243 + oc * 9 + (rem % 9)] = pack2(g, g);
            }
            __syncthreads();
#pragma unroll 1
            for (int cil = 0; cil < 16; cil++) {
                const float *xc = xb + (size_t)(cbase + cc + cil) * HWP;
                float a[6][3];
#pragma unroll
                for (int r = 0; r < 6; r++)
#pragma unroll
                    for (int c = 0; c < 3; c++)
                        a[r][c] = (rowok[r] && colok[c]) ? __ldg(xc + rowoff[r] + coloff[c]) : 0.f;
                u64 pv0[9], pv1[9];
#pragma unroll
                for (int kk = 0; kk < 9; kk++) {
                    int ki = kk / 3, kj = kk % 3;
                    pv0[kk] = pack2(a[ki][kj], a[ki + 2][kj]);
                    pv1[kk] = pack2(a[ki + 1][kj], a[ki + 3][kj]);
                }
                const u64 *wrow = &wshf[cil * 243];
#pragma unroll
                for (int kk = 0; kk < 9; kk++)
#pragma unroll
                    for (int oc = 0; oc < 27; oc++) {
                        u64 w = wrow[oc * 9 + kk];
                        acc0[oc] = ffma2(pv0[kk], w, acc0[oc]);
                        acc1[oc] = ffma2(pv1[kk], w, acc1[oc]);
                    }
            }
        }

        float *dst = &g_ompart[split][(size_t)b * 27 * HWP];
#pragma unroll
        for (int oc = 0; oc < 27; oc++) {
            float l0, h0, l1, h1;
            unpack2(acc0[oc], l0, h0);
            unpack2(acc1[oc], l1, h1);
            size_t base = (size_t)oc * HWP + y0 * WW + ox;
            dst[base] = l0;
            dst[base + WW] = l1;
            dst[base + 2 * WW] = h0;
            dst[base + 3 * WW] = h1;
        }
    } else if (blk < NB_OM + NB_TR) {
        // -------- NCHW -> NHWC transpose, fp16 --------
        int n = blk - NB_OM;
        int p0 = (n & 127) * 32;
        int c0 = ((n >> 7) & 7) * 32;
        int b = n >> 10;
        float (*tile)[33] = (float (*)[33])psm;
        int tx = t & 31, ty = t >> 5;
        const float *src = x + (size_t)b * CIN * HWP;
#pragma unroll
        for (int k = 0; k < 32; k += 8)
            tile[ty + k][tx] = src[(size_t)(c0 + ty + k) * HWP + p0 + tx];
        __syncthreads();
        __half *dh = g_xf + (size_t)b * HWP * CIN;
#pragma unroll
        for (int k = 0; k < 32; k += 8)
            dh[(size_t)(p0 + ty + k) * CIN + c0 + tx] = __float2half_rn(tile[tx][ty + k]);
    } else {
        // -------- w_dcn -> [kk][o][c] fp16 --------
        int blkL = blk - (NB_OM + NB_TR);
        int base = blkL * 4096 + t;
#pragma unroll
        for (int k = 0; k < 16; k++) {
            int i = base + k * 256;
            int c = i % CIN;
            int o = (i / CIN) % COUT;
            int kk = i / (CIN * COUT);
            g_wf[i] = __float2half_rn(wdcn[(size_t)(o * CIN + c) * KKN + kk]);
        }
    }
}

// ---------------- 2) sampling metadata ----------------
__global__ void k_meta(const float *__restrict__ bom) {
    int i = blockIdx.x * 256 + threadIdx.x;
    if (i >= BB * KKN * HWP) return;
    int p = i % HWP;
    int t = i / HWP;
    int kk = t % KKN;
    int b = t / KKN;
    int oy = p >> 6, ox = p & 63;
    size_t ob = (size_t)b * 27 * HWP;
#define OMSUM(ch) (g_ompart[0][ob + (size_t)(ch) * HWP + p] + g_ompart[1][ob + (size_t)(ch) * HWP + p] + \
                   g_ompart[2][ob + (size_t)(ch) * HWP + p] + g_ompart[3][ob + (size_t)(ch) * HWP + p])
    float dy = OMSUM(kk) + bom[kk];
    float dx = OMSUM(9 + kk) + bom[9 + kk];
    float mz = OMSUM(18 + kk) + bom[18 + kk];
#undef OMSUM
    float m = 1.f / (1.f + expf(-mz));
    int ki = kk / 3, kj = kk % 3;
    float py = (float)(oy - 1 + ki) + dy;
    float px = (float)(ox - 1 + kj) + dx;
    float y0f = floorf(py), x0f = floorf(px);
    float ly = py - y0f, lx = px - x0f;
    int y0 = (int)y0f, x0 = (int)x0f;
    int y1 = y0 + 1, x1 = x0 + 1;

    float v00 = (y0 >= 0 && y0 < HH && x0 >= 0 && x0 < WW) ? 1.f : 0.f;
    float v01 = (y0 >= 0 && y0 < HH && x1 >= 0 && x1 < WW) ? 1.f : 0.f;
    float v10 = (y1 >= 0 && y1 < HH && x0 >= 0 && x0 < WW) ? 1.f : 0.f;
    float v11 = (y1 >= 0 && y1 < HH && x1 >= 0 && x1 < WW) ? 1.f : 0.f;
    int cy0 = min(max(y0, 0), HH - 1), cy1 = min(max(y1, 0), HH - 1);
    int cx0 = min(max(x0, 0), WW - 1), cx1 = min(max(x1, 0), WW - 1);

    g_mw[i] = make_float4((1.f - ly) * (1.f - lx) * m * v00,
                          (1.f - ly) * lx * m * v01,
                          ly * (1.f - lx) * m * v10,
                          ly * lx * m * v11);
    g_mi[i] = make_int4((cy0 * WW + cx0) * COUT, (cy0 * WW + cx1) * COUT,
                        (cy1 * WW + cx0) * COUT, (cy1 * WW + cx1) * COUT);
}

// ---------------- 3) persistent dense GEMMs: single fp16 mma.sync ----------------
#define NT 4608
#define NSMG 296
#define KC 64
#define STAGE_BYTES 32768
#define X_OFF 0
#define W_OFF 16384
#define SM_TOT (2 * STAGE_BYTES)

struct TileInfo {
    const __half *xf, *wf;
    size_t yoff;
};
__device__ __forceinline__ TileInfo tile_decode(int ti) {
    int inner = ti % 18;
    int outer = ti / 18;
    int b = outer >> 5;
    int p0 = (outer & 31) * 128;
    int kk = inner >> 1;
    int o0 = (inner & 1) * 128;
    TileInfo r;
    r.xf = g_xf + ((size_t)b * HWP + p0) * CIN;
    r.wf = g_wf + ((size_t)kk * COUT + o0) * CIN;
    r.yoff = (((size_t)(kk * BB + b) * HWP + p0) * COUT) + o0;
    return r;
}

__global__ void __launch_bounds__(256, 2) k_gemm() {
    extern __shared__ char smem[];
    uint32_t sb = smem_u32(smem);
    int tid = threadIdx.x;
    int wid = tid >> 5, lane = tid & 31;
    int bid = blockIdx.x;

    int ntiles = (NT - bid + NSMG - 1) / NSMG;
    int NC = ntiles * 4;

    int lsw4[4], lrow4[4], latom4[4];
#pragma unroll
    for (int k2 = 0; k2 < 4; k2++) {
        int idx = tid + k2 * 256;
        lrow4[k2] = idx >> 3;
        latom4[k2] = idx & 7;
        lsw4[k2] = SWZ((idx >> 3) * 128 + (idx & 7) * 16);
    }

#define ISSUE_CHUNK(n) do { \
        int _ti = bid + ((n) >> 2) * NSMG; \
        TileInfo _t = tile_decode(_ti); \
        int _c0 = ((n) & 3) * KC; \
        uint32_t _stb = sb + ((n) & 1) * STAGE_BYTES; \
        _Pragma("unroll") \
        for (int k2 = 0; k2 < 4; k2++) { \
            size_t g = (size_t)lrow4[k2] * CIN + _c0 + latom4[k2] * 8; \
            CP_ASYNC16(_stb + X_OFF + lsw4[k2], _t.xf + g); \
            CP_ASYNC16(_stb + W_OFF + lsw4[k2], _t.wf + g); \
        } \
    } while (0)

    int wp = wid >> 2;
    int wo = wid & 3;
    int abase = (wp * 64 + (lane & 15)) * 128 + ((lane >> 4) * 8) * 2;
    int bbase = (wo * 32 + (lane & 7)) * 128 + (((lane >> 3) & 1) * 8) * 2;

    float d[4][4][4];
#pragma unroll
    for (int mt = 0; mt < 4; mt++)
#pragma unroll
        for (int nt = 0; nt < 4; nt++)
#pragma unroll
            for (int j = 0; j < 4; j++) d[mt][nt][j] = 0.f;

    ISSUE_CHUNK(0); CP_COMMIT();
    if (NC > 1) ISSUE_CHUNK(1);
    CP_COMMIT();

    for (int n = 0; n < NC; n++) {
        if (n + 1 < NC) { CP_WAIT1(); } else { CP_WAIT0(); }
        __syncthreads();

        uint32_t stb = sb + (n & 1) * STAGE_BYTES;
#pragma unroll
        for (int ks = 0; ks < 4; ks++) {
            uint32_t ah[4][4];
#pragma unroll
            for (int mt = 0; mt < 4; mt++)
                LDSM_X4(ah[mt], stb + X_OFF + SWZ(abase + mt * 2048 + ks * 32));
            uint32_t bh[4][2];
#pragma unroll
            for (int nt = 0; nt < 4; nt++)
                LDSM_X2(bh[nt], stb + W_OFF + SWZ(bbase + nt * 1024 + ks * 32));
#pragma unroll
            for (int mt = 0; mt < 4; mt++)
#pragma unroll
                for (int nt = 0; nt < 4; nt++)
                    MMA_FP16(d[mt][nt], ah[mt], bh[nt]);
        }
        __syncthreads();

        if (n + 2 < NC) ISSUE_CHUNK(n + 2);
        CP_COMMIT();

        if ((n & 3) == 3) {
            int ti = bid + (n >> 2) * NSMG;
            TileInfo tinfo = tile_decode(ti);
            __half *yo = g_y + tinfo.yoff;
#pragma unroll
            for (int mt = 0; mt < 4; mt++) {
                int r0 = wp * 64 + mt * 16 + (lane >> 2);
#pragma unroll
                for (int nt = 0; nt < 4; nt++) {
                    int c = wo * 32 + nt * 8 + (lane & 3) * 2;
                    *(__half2 *)(yo + (size_t)r0 * COUT + c) = __floats2half2_rn(d[mt][nt][0], d[mt][nt][1]);
                    *(__half2 *)(yo + (size_t)(r0 + 8) * COUT + c) = __floats2half2_rn(d[mt][nt][2], d[mt][nt][3]);
                    d[mt][nt][0] = 0.f; d[mt][nt][1] = 0.f; d[mt][nt][2] = 0.f; d[mt][nt][3] = 0.f;
                }
            }
        }
    }
#undef ISSUE_CHUNK
}

// ---------------- 4) gather-axpy assembly: out[b][o][p] ----------------
__global__ void __launch_bounds__(512) k_out(const float *__restrict__ bdcn,
                                             float *__restrict__ out) {
    __shared__ float4 smw[KKN][16];
    __shared__ int4 smi[KKN][16];
    __shared__ float st[16][257];
    int b = blockIdx.y;
    int p0 = blockIdx.x * 16;
    int t = threadIdx.x;

    for (int j = t; j < KKN * 16; j += 512) {
        int kk = j / 16, p = j % 16;
        int gi = (b * KKN + kk) * HWP + p0 + p;
        smw[kk][p] = g_mw[gi];
        smi[kk][p] = g_mi[gi];
    }
    __syncthreads();

    int pl = t >> 5;
    int ol = (t & 31) * 8;

    u64 a[4];
    {
        float4 b0 = *(const float4 *)(bdcn + ol);
        float4 b1 = *(const float4 *)(bdcn + ol + 4);
        a[0] = pack2(b0.x, b0.y); a[1] = pack2(b0.z, b0.w);
        a[2] = pack2(b1.x, b1.y); a[3] = pack2(b1.z, b1.w);
    }

#define CORNER(W, OFFS) do { \
        u64 ww = pack2((W), (W)); \
        uint4 v = __ldg((const uint4 *)(yk + (OFFS) + ol)); \
        const __half2 *hp = (const __half2 *)&v; \
        _Pragma("unroll") \
        for (int j = 0; j < 4; j++) { \
            float2 f = __half22float2(hp[j]); \
            a[j] = ffma2(pack2(f.x, f.y), ww, a[j]); \
        } \
    } while (0)

#pragma unroll 1
    for (int kk = 0; kk < KKN; kk++) {
        const __half *yk = g_y + (size_t)(kk * BB + b) * HWP * COUT;
        float4 w = smw[kk][pl];
        int4 ii = smi[kk][pl];
        CORNER(w.x, ii.x);
        CORNER(w.y, ii.y);
        CORNER(w.z, ii.z);
        CORNER(w.w, ii.w);
    }
#undef CORNER

    float *sr = &st[pl][ol];
#pragma unroll
    for (int j = 0; j < 4; j++) {
        float lo, hi; unpack2(a[j], lo, hi);
        sr[2 * j] = lo; sr[2 * j + 1] = hi;
    }
    __syncthreads();
    for (int idx = t; idx < 4096; idx += 512) {
        int o = idx >> 4, p2 = idx & 15;
        out[((size_t)b * COUT + o) * HWP + p0 + p2] = st[p2][o];
    }
}

// ---------------- launch ----------------
extern "C" void kernel_launch(void *const *d_in, const int *in_sizes, int n_in,
                              void *d_out, int out_size) {
    const float *x = (const float *)d_in[0];
    const float *w_om = (const float *)d_in[1];
    const float *b_om = (const float *)d_in[2];
    const float *w_dcn = (const float *)d_in[3];
    const float *b_dcn = (const float *)d_in[4];
    float *out = (float *)d_out;

    static int smem_set = 0;
    if (!smem_set) {
        cudaFuncSetAttribute(k_gemm, cudaFuncAttributeMaxDynamicSharedMemorySize, SM_TOT);
        smem_set = 1;
    }

    k_prep<<<NB_PREP, 256>>>(x, w_om, w_dcn);

    k_meta<<<(BB * KKN * HWP + 255) / 256, 256>>>(b_om);

    k_gemm<<<NSMG, 256, SM_TOT>>>();

    k_out<<<dim3(HWP / 16, BB), 512>>>(b_dcn, out);
}